// round 3
// baseline (speedup 1.0000x reference)
#include <cuda_runtime.h>

typedef unsigned long long ull;

#define BN 8192
#define TN 2048

// Transposed excitation scratch: [T][B] layout for coalesced per-step loads.
__device__ float g_excT[(size_t)TN * BN];

__device__ __forceinline__ float tanha(float x) {
    float y; asm("tanh.approx.f32 %0, %1;" : "=f"(y) : "f"(x)); return y;
}
__device__ __forceinline__ ull pack2(float lo, float hi) {
    ull r; asm("mov.b64 %0, {%1, %2};" : "=l"(r) : "f"(lo), "f"(hi)); return r;
}
__device__ __forceinline__ void unpack2(ull v, float& lo, float& hi) {
    asm("mov.b64 {%0, %1}, %2;" : "=f"(lo), "=f"(hi) : "l"(v));
}
// Packed dual-FMA (Blackwell f32x2 pipe — 2 fp32 FMAs per issue).
__device__ __forceinline__ void ffma2(ull& d, ull a, ull b) {
    asm("fma.rn.f32x2 %0, %1, %2, %0;" : "+l"(d) : "l"(a), "l"(b));
}

// exc[B][T] -> g_excT[T][B]
__global__ void transpose_exc(const float* __restrict__ exc) {
    __shared__ float tile[32][33];
    int t0 = blockIdx.x * 32, b0 = blockIdx.y * 32;
    int tx = threadIdx.x, ty = threadIdx.y;
#pragma unroll
    for (int i = 0; i < 32; i += 8)
        tile[ty + i][tx] = exc[(size_t)(b0 + ty + i) * TN + t0 + tx];
    __syncthreads();
#pragma unroll
    for (int i = 0; i < 32; i += 8)
        g_excT[(size_t)(t0 + ty + i) * BN + b0 + tx] = tile[tx][ty + i];
}

// 8 threads per muscle. 64-thread CTAs -> 8 muscles/CTA, 1024 CTAs,
// 2048 warps (3.46/SMSP) for latency hiding. Each thread owns 8 hidden
// neurons (layer 1) and 8 layer-2 outputs; the hidden vector is exchanged
// through a small SMEM staging buffer instead of shuffles.
__global__ __launch_bounds__(64, 7) void ode_kernel(
    const float* __restrict__ init, const float* __restrict__ tspan,
    const float* __restrict__ W1, const float* __restrict__ b1,
    const float* __restrict__ W2, const float* __restrict__ b2,
    const float* __restrict__ W3, const float* __restrict__ b3,
    float* __restrict__ out)
{
    __shared__ __align__(16) float sW1[256];
    __shared__ __align__(16) float sb1[64];
    __shared__ __align__(16) float sW2[4096];
    __shared__ __align__(16) float sb2[64];
    __shared__ __align__(16) float sW3[192];
    __shared__ __align__(16) float sb3[4];
    // h staging: 8 muscles x 64 h values; row stride 72 floats (16B aligned,
    // conflict-free broadcast reads across the 4 muscles of a warp).
    __shared__ __align__(16) float hst[8 * 72];

    int tid = threadIdx.x;
    for (int i = tid; i < 256;  i += 64) sW1[i] = W1[i];
    for (int i = tid; i < 64;   i += 64) sb1[i] = b1[i];
    for (int i = tid; i < 4096; i += 64) sW2[i] = W2[i];
    for (int i = tid; i < 64;   i += 64) sb2[i] = b2[i];
    for (int i = tid; i < 192;  i += 64) sW3[i] = W3[i];
    if (tid < 4) sb3[tid] = (tid < 3) ? b3[tid] : 0.0f;
    __syncthreads();

    const int sub  = tid & 7;            // 8-neuron block owned by this thread
    const int mloc = tid >> 3;           // muscle slot within CTA (0..7)
    const int b    = blockIdx.x * 8 + mloc;
    float* hrow = hst + mloc * 72;

    float y0 = init[b * 3 + 0];
    float y1 = init[b * 3 + 1];
    float y2 = init[b * 3 + 2];
    if (sub == 0) { out[b*3+0] = y0; out[b*3+1] = y1; out[b*3+2] = y2; }

    // k1 at step 0 uses exc[:, 0] (searchsorted idx = clip(-1) = 0)
    float ep = g_excT[b];
    float tprev = tspan[0];

#pragma unroll 1
    for (int it = 0; it < TN - 1; it++) {
        float ec    = g_excT[(size_t)it * BN + b];   // exc[:, it] for k2/k3/k4
        float tnext = tspan[it + 1];
        float dt    = tnext - tprev;
        tprev = tnext;
        float hd  = 0.5f * dt;
        float a0 = y0, a1 = y1, a2 = y2;
        float s0 = 0.f, s1 = 0.f, s2 = 0.f;

#pragma unroll 1
        for (int s = 0; s < 4; s++) {
            float e = (s == 0) ? ep : ec;

            // ---------------- physics_rhs (clipped state) ----------------
            float lM   = fminf(fmaxf(a0, 0.0445f), 0.1424f);
            float act  = fminf(fmaxf(a1, 0.01f), 1.0f);
            float fat  = fminf(fmaxf(a2, 0.0f), 1.0f);
            float aeff = act * (1.0f - fat);
            // L0*sin(PENN0) = 0.089*sin(0.0873)
            float sinp = fminf(__fdividef(0.00775983457f, lM), 0.99f);
            float cosp = sqrtf(1.0f - sinp * sinp);
            // LMT_DEFAULT = 0.126 + 0.089*cos(0.0873)
            float lT   = 0.214661068f - lM * cosp;
            float epsT = (lT - 0.126f) * (1.0f / 0.126f);
            float fT   = (epsT > 0.0f) ? 0.2f * (__expf(35.0f * epsT) - 1.0f) : 0.0f;
            float lN   = lM * (1.0f / 0.089f);
            float ddv  = lN - 1.0f;
            float fL   = __expf(-ddv * ddv * (1.0f / 0.45f));
            float fPE  = (lN > 1.0f)
                       ? (__expf(ddv * (5.0f / 0.6f)) - 1.0f) * (1.0f / 147.4131591f)
                       : 0.0f;
            float fV   = __fdividef(__fdividef(fT, cosp) - fPE, aeff * fL + 0.001f);
            float vN   = fminf(fmaxf(__fdividef(fV - 1.0f, 1.0f + fabsf(fV) * 4.0f),
                                     -1.0f), 1.5f);
            float k0   = 0.89f * vN;                       // VMAX*L0*vN
            float tau  = (e > act) ? 0.01f * (0.5f + 1.5f * act)
                                   : __fdividef(0.04f, 0.5f + 1.5f * act);
            float k1d  = __fdividef(e - act, tau);
            float k2d  = 0.01f * aeff * (1.0f - fat) - 0.002f * (1.0f - aeff) * fat;

            // ---------------- neural correction (raw state) ----------------
            // layer 1: this thread computes h[sub*8 .. sub*8+7]
            float hv[8];
            {
                ull xx0 = pack2(a0, a0);
                ull xx1 = pack2(a1, a1);
                ull xx2 = pack2(a2, a2);
                ull xx3 = pack2(e,  e);
                ulonglong2 bq0 = *(const ulonglong2*)(sb1 + sub * 8);
                ulonglong2 bq1 = *(const ulonglong2*)(sb1 + sub * 8 + 4);
                ull acc01 = bq0.x, acc23 = bq0.y, acc45 = bq1.x, acc67 = bq1.y;
#pragma unroll
                for (int r = 0; r < 4; r++) {
                    ulonglong2 wa = *(const ulonglong2*)(sW1 + r * 64 + sub * 8);
                    ulonglong2 wb = *(const ulonglong2*)(sW1 + r * 64 + sub * 8 + 4);
                    ull x = (r == 0) ? xx0 : (r == 1) ? xx1 : (r == 2) ? xx2 : xx3;
                    ffma2(acc01, x, wa.x); ffma2(acc23, x, wa.y);
                    ffma2(acc45, x, wb.x); ffma2(acc67, x, wb.y);
                }
                unpack2(acc01, hv[0], hv[1]);
                unpack2(acc23, hv[2], hv[3]);
                unpack2(acc45, hv[4], hv[5]);
                unpack2(acc67, hv[6], hv[7]);
#pragma unroll
                for (int j = 0; j < 8; j++) hv[j] = tanha(hv[j]);
            }
            // publish h to staging (WAR: previous stage's reads done -> sync)
            __syncwarp();
            {
                float4 v0 = make_float4(hv[0], hv[1], hv[2], hv[3]);
                float4 v1 = make_float4(hv[4], hv[5], hv[6], hv[7]);
                *(float4*)(hrow + sub * 8)     = v0;
                *(float4*)(hrow + sub * 8 + 4) = v1;
            }
            __syncwarp();

            // layer 2: outputs sub*8 .. sub*8+7, 4 packed accumulators
            ull acc2[4];
            {
                ulonglong2 v0 = *(const ulonglong2*)(sb2 + sub * 8);
                ulonglong2 v1 = *(const ulonglong2*)(sb2 + sub * 8 + 4);
                acc2[0] = v0.x; acc2[1] = v0.y; acc2[2] = v1.x; acc2[3] = v1.y;
            }
#pragma unroll
            for (int kb = 0; kb < 16; kb++) {
                float4 hq = *(const float4*)(hrow + kb * 4);
#pragma unroll
                for (int kk = 0; kk < 4; kk++) {
                    int k = kb * 4 + kk;
                    float hk = (kk == 0) ? hq.x : (kk == 1) ? hq.y
                             : (kk == 2) ? hq.z : hq.w;
                    ull hh = pack2(hk, hk);
                    ulonglong2 wa = *(const ulonglong2*)(sW2 + k * 64 + sub * 8);
                    ulonglong2 wb = *(const ulonglong2*)(sW2 + k * 64 + sub * 8 + 4);
                    ffma2(acc2[0], hh, wa.x); ffma2(acc2[1], hh, wa.y);
                    ffma2(acc2[2], hh, wb.x); ffma2(acc2[3], hh, wb.y);
                }
            }
            // layer 3 partials over this thread's 8 outputs
            float p0 = 0.f, p1 = 0.f, p2 = 0.f;
            {
                // 24 consecutive W3 floats for rows sub*8..sub*8+7 (16B aligned)
                const float4* w3q = (const float4*)(sW3 + sub * 24);
                float4 q0 = w3q[0], q1 = w3q[1], q2 = w3q[2],
                       q3 = w3q[3], q4 = w3q[4], q5 = w3q[5];
                float o[8];
                unpack2(acc2[0], o[0], o[1]);
                unpack2(acc2[1], o[2], o[3]);
                unpack2(acc2[2], o[4], o[5]);
                unpack2(acc2[3], o[6], o[7]);
#pragma unroll
                for (int j = 0; j < 8; j++) o[j] = tanha(o[j]);
                p0 = fmaf(o[0], q0.x, p0); p1 = fmaf(o[0], q0.y, p1); p2 = fmaf(o[0], q0.z, p2);
                p0 = fmaf(o[1], q0.w, p0); p1 = fmaf(o[1], q1.x, p1); p2 = fmaf(o[1], q1.y, p2);
                p0 = fmaf(o[2], q1.z, p0); p1 = fmaf(o[2], q1.w, p1); p2 = fmaf(o[2], q2.x, p2);
                p0 = fmaf(o[3], q2.y, p0); p1 = fmaf(o[3], q2.z, p1); p2 = fmaf(o[3], q2.w, p2);
                p0 = fmaf(o[4], q3.x, p0); p1 = fmaf(o[4], q3.y, p1); p2 = fmaf(o[4], q3.z, p2);
                p0 = fmaf(o[5], q3.w, p0); p1 = fmaf(o[5], q4.x, p1); p2 = fmaf(o[5], q4.y, p2);
                p0 = fmaf(o[6], q4.z, p0); p1 = fmaf(o[6], q4.w, p1); p2 = fmaf(o[6], q5.x, p2);
                p0 = fmaf(o[7], q5.y, p0); p1 = fmaf(o[7], q5.z, p1); p2 = fmaf(o[7], q5.w, p2);
            }
            // reduce across the 8 lanes of this muscle
            p0 += __shfl_xor_sync(0xffffffffu, p0, 1);
            p0 += __shfl_xor_sync(0xffffffffu, p0, 2);
            p0 += __shfl_xor_sync(0xffffffffu, p0, 4);
            p1 += __shfl_xor_sync(0xffffffffu, p1, 1);
            p1 += __shfl_xor_sync(0xffffffffu, p1, 2);
            p1 += __shfl_xor_sync(0xffffffffu, p1, 4);
            p2 += __shfl_xor_sync(0xffffffffu, p2, 1);
            p2 += __shfl_xor_sync(0xffffffffu, p2, 2);
            p2 += __shfl_xor_sync(0xffffffffu, p2, 4);

            k0  += 0.2f * (0.1f * tanha(p0 + sb3[0]));
            k1d += 0.2f * (0.1f * tanha(p1 + sb3[1]));
            k2d += 0.2f * (0.1f * tanha(p2 + sb3[2]));

            // ---------------- RK4 combine ----------------
            float wgt = (s == 1 || s == 2) ? 2.0f : 1.0f;
            s0 = fmaf(wgt, k0,  s0);
            s1 = fmaf(wgt, k1d, s1);
            s2 = fmaf(wgt, k2d, s2);
            float st = (s < 2) ? hd : dt;   // stage input offsets (s==3 unused)
            a0 = y0 + st * k0;
            a1 = y1 + st * k1d;
            a2 = y2 + st * k2d;
        }

        float w6 = dt * (1.0f / 6.0f);
        y0 += w6 * s0; y1 += w6 * s1; y2 += w6 * s2;

        if (sub == 0) {
            size_t o = (size_t)(it + 1) * (BN * 3) + (size_t)b * 3;
            out[o] = y0; out[o + 1] = y1; out[o + 2] = y2;
        }
        ep = ec;
    }
}

extern "C" void kernel_launch(void* const* d_in, const int* in_sizes, int n_in,
                              void* d_out, int out_size) {
    const float* init = (const float*)d_in[0];
    const float* exc  = (const float*)d_in[1];
    const float* ts   = (const float*)d_in[2];
    const float* W1   = (const float*)d_in[3];
    const float* b1   = (const float*)d_in[4];
    const float* W2   = (const float*)d_in[5];
    const float* b2   = (const float*)d_in[6];
    const float* W3   = (const float*)d_in[7];
    const float* b3   = (const float*)d_in[8];
    float* out = (float*)d_out;

    dim3 tb(32, 8);
    dim3 tg(TN / 32, BN / 32);
    transpose_exc<<<tg, tb>>>(exc);
    ode_kernel<<<BN / 8, 64>>>(init, ts, W1, b1, W2, b2, W3, b3, out);
}

// round 4
// speedup vs baseline: 2.1870x; 2.1870x over previous
#include <cuda_runtime.h>

typedef unsigned long long ull;

#define BN 8192
#define TN 2048
#define MPC 16   // muscles per CTA

// Transposed excitation scratch: [T][B] layout for coalesced per-step loads.
__device__ float g_excT[(size_t)TN * BN];

__device__ __forceinline__ float tanha(float x) {
    float y; asm("tanh.approx.f32 %0, %1;" : "=f"(y) : "f"(x)); return y;
}
__device__ __forceinline__ ull pack2(float lo, float hi) {
    ull r; asm("mov.b64 %0, {%1, %2};" : "=l"(r) : "f"(lo), "f"(hi)); return r;
}
__device__ __forceinline__ void unpack2(ull v, float& lo, float& hi) {
    asm("mov.b64 {%0, %1}, %2;" : "=f"(lo), "=f"(hi) : "l"(v));
}
// Packed dual-FMA (Blackwell f32x2 pipe — 2 fp32 FMAs per issue).
__device__ __forceinline__ void ffma2(ull& d, ull a, ull b) {
    asm("fma.rn.f32x2 %0, %1, %2, %0;" : "+l"(d) : "l"(a), "l"(b));
}

// exc[B][T] -> g_excT[T][B]
__global__ void transpose_exc(const float* __restrict__ exc) {
    __shared__ float tile[32][33];
    int t0 = blockIdx.x * 32, b0 = blockIdx.y * 32;
    int tx = threadIdx.x, ty = threadIdx.y;
#pragma unroll
    for (int i = 0; i < 32; i += 8)
        tile[ty + i][tx] = exc[(size_t)(b0 + ty + i) * TN + t0 + tx];
    __syncthreads();
#pragma unroll
    for (int i = 0; i < 32; i += 8)
        g_excT[(size_t)(t0 + ty + i) * BN + b0 + tx] = tile[tx][ty + i];
}

// Weight-stationary formulation.
// CTA = 64 threads (2 warps), 16 muscles. Thread tid owns output neuron
// j = tid (0..63): W1 column (4 regs), b1, b2, and the whole W2 column as
// 32 packed f32x2 registers. The hidden vector h[m][k] is staged in smem
// and read with BROADCAST LDS.128 (1 wavefront). Lanes 0..7 of each warp
// additionally own one muscle each for physics / layer-3 / RK4 state.
__global__ __launch_bounds__(64) void ode_kernel(
    const float* __restrict__ init, const float* __restrict__ tspan,
    const float* __restrict__ W1, const float* __restrict__ b1,
    const float* __restrict__ W2, const float* __restrict__ b2,
    const float* __restrict__ W3, const float* __restrict__ b3,
    float* __restrict__ out)
{
    __shared__ __align__(16) float h_s[MPC * 72];
    __shared__ __align__(16) float o_s[MPC * 72];
    __shared__ __align__(16) float x_s[MPC * 4];
    __shared__ __align__(16) float w3t[3][68];   // transposed W3, row-padded
    __shared__ __align__(16) float sb3[4];

    const int tid  = threadIdx.x;
    const int lane = tid & 31;
    const int warp = tid >> 5;
    const int jg   = tid;                 // output-neuron index 0..63

    // one-time weight staging
    for (int i = tid; i < 192; i += 64) w3t[i % 3][i / 3] = W3[i];
    if (tid < 3) sb3[tid] = b3[tid];
    if (tid == 3) sb3[3] = 0.0f;

    const float w10 = W1[jg], w11 = W1[64 + jg],
                w12 = W1[128 + jg], w13 = W1[192 + jg];
    const float b1j = b1[jg];
    const float b2j = b2[jg];
    ull w2p[32];
#pragma unroll
    for (int i = 0; i < 32; i++)
        w2p[i] = pack2(W2[(2 * i) * 64 + jg], W2[(2 * i + 1) * 64 + jg]);

    const bool owner = lane < 8;
    const int  mo = warp * 8 + lane;               // muscle owned (if owner)
    const int  bo = blockIdx.x * MPC + mo;

    float y0 = 0.f, y1 = 0.f, y2 = 0.f, ep = 0.f, tprev = 0.f;
    if (owner) {
        y0 = init[bo * 3 + 0];
        y1 = init[bo * 3 + 1];
        y2 = init[bo * 3 + 2];
        out[bo * 3 + 0] = y0; out[bo * 3 + 1] = y1; out[bo * 3 + 2] = y2;
        ep = g_excT[bo];                 // k1 at step 0 uses exc[:, 0]
        tprev = tspan[0];
        *(float4*)(x_s + mo * 4) = make_float4(y0, y1, y2, ep);
    }
    __syncthreads();

#pragma unroll 1
    for (int it = 0; it < TN - 1; it++) {
        float ec = 0.f, dt = 0.f, hd = 0.f;
        float a0 = y0, a1 = y1, a2 = y2;
        float s0 = 0.f, s1 = 0.f, s2 = 0.f;
        if (owner) {
            ec = g_excT[(size_t)it * BN + bo];     // exc[:, it] for k2/k3/k4
            float tnext = tspan[it + 1];
            dt = tnext - tprev;
            tprev = tnext;
            hd = 0.5f * dt;
        }

#pragma unroll 1
        for (int sg = 0; sg < 4; sg++) {
            // ---- slot 1: layer-1 (all threads) + physics (owner lanes) ----
#pragma unroll 4
            for (int m = 0; m < MPC; m++) {
                float4 x = *(const float4*)(x_s + m * 4);   // broadcast
                float t = fmaf(x.x, w10,
                          fmaf(x.y, w11,
                          fmaf(x.z, w12,
                          fmaf(x.w, w13, b1j))));
                h_s[m * 72 + jg] = tanha(t);
            }

            float k0 = 0.f, k1d = 0.f, k2d = 0.f, e = 0.f;
            if (owner) {
                e = (sg == 0) ? ep : ec;
                float lM   = fminf(fmaxf(a0, 0.0445f), 0.1424f);
                float act  = fminf(fmaxf(a1, 0.01f), 1.0f);
                float fat  = fminf(fmaxf(a2, 0.0f), 1.0f);
                float aeff = act * (1.0f - fat);
                // L0*sin(PENN0) = 0.089*sin(0.0873)
                float sinp = fminf(__fdividef(0.00775983457f, lM), 0.99f);
                float cosp = sqrtf(1.0f - sinp * sinp);
                // LMT_DEFAULT = 0.126 + 0.089*cos(0.0873)
                float lT   = 0.214661068f - lM * cosp;
                float epsT = (lT - 0.126f) * (1.0f / 0.126f);
                float fT   = (epsT > 0.0f) ? 0.2f * (__expf(35.0f * epsT) - 1.0f) : 0.0f;
                float lN   = lM * (1.0f / 0.089f);
                float ddv  = lN - 1.0f;
                float fL   = __expf(-ddv * ddv * (1.0f / 0.45f));
                float fPE  = (lN > 1.0f)
                           ? (__expf(ddv * (5.0f / 0.6f)) - 1.0f) * (1.0f / 147.4131591f)
                           : 0.0f;
                float fV   = __fdividef(__fdividef(fT, cosp) - fPE, aeff * fL + 0.001f);
                float vN   = fminf(fmaxf(__fdividef(fV - 1.0f, 1.0f + fabsf(fV) * 4.0f),
                                         -1.0f), 1.5f);
                k0   = 0.89f * vN;                        // VMAX*L0*vN
                float tau = (e > act) ? 0.01f * (0.5f + 1.5f * act)
                                      : __fdividef(0.04f, 0.5f + 1.5f * act);
                k1d  = __fdividef(e - act, tau);
                k2d  = 0.01f * aeff * (1.0f - fat) - 0.002f * (1.0f - aeff) * fat;
            }
            __syncthreads();

            // ---- slot 2: layer-2, weight-stationary, 2 muscles at a time ----
#pragma unroll 1
            for (int m = 0; m < MPC; m += 2) {
                const ulonglong2* hA = (const ulonglong2*)(h_s + m * 72);
                const ulonglong2* hB = (const ulonglong2*)(h_s + (m + 1) * 72);
                ull aA0 = 0, aA1 = 0, aB0 = 0, aB1 = 0;
#pragma unroll
                for (int q = 0; q < 16; q++) {
                    ulonglong2 hqA = hA[q];      // broadcast LDS.128
                    ulonglong2 hqB = hB[q];
                    ffma2(aA0, hqA.x, w2p[2 * q]);
                    ffma2(aA1, hqA.y, w2p[2 * q + 1]);
                    ffma2(aB0, hqB.x, w2p[2 * q]);
                    ffma2(aB1, hqB.y, w2p[2 * q + 1]);
                }
                float u0, u1, u2, u3;
                unpack2(aA0, u0, u1); unpack2(aA1, u2, u3);
                o_s[m * 72 + jg] = tanha(((u0 + u1) + (u2 + u3)) + b2j);
                unpack2(aB0, u0, u1); unpack2(aB1, u2, u3);
                o_s[(m + 1) * 72 + jg] = tanha(((u0 + u1) + (u2 + u3)) + b2j);
            }
            __syncthreads();

            // ---- slot 3: layer-3 + RK4 (owner lanes) ----
            if (owner) {
                const ulonglong2* orow = (const ulonglong2*)(o_s + mo * 72);
                const ulonglong2* w3r0 = (const ulonglong2*)(w3t[0]);
                const ulonglong2* w3r1 = (const ulonglong2*)(w3t[1]);
                const ulonglong2* w3r2 = (const ulonglong2*)(w3t[2]);
                ull P0 = 0, P1 = 0, P2 = 0;
#pragma unroll
                for (int q = 0; q < 16; q++) {
                    ulonglong2 oq = orow[q];
                    ulonglong2 wq0 = w3r0[q], wq1 = w3r1[q], wq2 = w3r2[q];
                    ffma2(P0, oq.x, wq0.x); ffma2(P0, oq.y, wq0.y);
                    ffma2(P1, oq.x, wq1.x); ffma2(P1, oq.y, wq1.y);
                    ffma2(P2, oq.x, wq2.x); ffma2(P2, oq.y, wq2.y);
                }
                float p0a, p0b, p1a, p1b, p2a, p2b;
                unpack2(P0, p0a, p0b);
                unpack2(P1, p1a, p1b);
                unpack2(P2, p2a, p2b);
                float p0 = p0a + p0b, p1 = p1a + p1b, p2 = p2a + p2b;

                k0  += 0.2f * (0.1f * tanha(p0 + sb3[0]));
                k1d += 0.2f * (0.1f * tanha(p1 + sb3[1]));
                k2d += 0.2f * (0.1f * tanha(p2 + sb3[2]));

                float wgt = (sg == 1 || sg == 2) ? 2.0f : 1.0f;
                s0 = fmaf(wgt, k0,  s0);
                s1 = fmaf(wgt, k1d, s1);
                s2 = fmaf(wgt, k2d, s2);

                if (sg < 3) {
                    float st = (sg < 2) ? hd : dt;
                    a0 = y0 + st * k0;
                    a1 = y1 + st * k1d;
                    a2 = y2 + st * k2d;
                    *(float4*)(x_s + mo * 4) = make_float4(a0, a1, a2, ec);
                } else {
                    float w6 = dt * (1.0f / 6.0f);
                    y0 += w6 * s0; y1 += w6 * s1; y2 += w6 * s2;
                    size_t o = (size_t)(it + 1) * (BN * 3) + (size_t)bo * 3;
                    out[o] = y0; out[o + 1] = y1; out[o + 2] = y2;
                    // next step's k1 excitation = this step's ec
                    *(float4*)(x_s + mo * 4) = make_float4(y0, y1, y2, ec);
                }
            }
            __syncthreads();
        }
        if (owner) ep = ec;
    }
}

extern "C" void kernel_launch(void* const* d_in, const int* in_sizes, int n_in,
                              void* d_out, int out_size) {
    const float* init = (const float*)d_in[0];
    const float* exc  = (const float*)d_in[1];
    const float* ts   = (const float*)d_in[2];
    const float* W1   = (const float*)d_in[3];
    const float* b1   = (const float*)d_in[4];
    const float* W2   = (const float*)d_in[5];
    const float* b2   = (const float*)d_in[6];
    const float* W3   = (const float*)d_in[7];
    const float* b3   = (const float*)d_in[8];
    float* out = (float*)d_out;

    dim3 tb(32, 8);
    dim3 tg(TN / 32, BN / 32);
    transpose_exc<<<tg, tb>>>(exc);
    ode_kernel<<<BN / MPC, 64>>>(init, ts, W1, b1, W2, b2, W3, b3, out);
}

// round 5
// speedup vs baseline: 2.5452x; 1.1638x over previous
#include <cuda_runtime.h>

typedef unsigned long long ull;

#define BN 8192
#define TN 2048
#define MPC 8    // muscles per CTA

// Transposed excitation scratch: [T][B] layout for coalesced per-step loads.
__device__ float g_excT[(size_t)TN * BN];

__device__ __forceinline__ float tanha(float x) {
    float y; asm("tanh.approx.f32 %0, %1;" : "=f"(y) : "f"(x)); return y;
}
__device__ __forceinline__ ull pack2(float lo, float hi) {
    ull r; asm("mov.b64 %0, {%1, %2};" : "=l"(r) : "f"(lo), "f"(hi)); return r;
}
__device__ __forceinline__ void unpack2(ull v, float& lo, float& hi) {
    asm("mov.b64 {%0, %1}, %2;" : "=f"(lo), "=f"(hi) : "l"(v));
}
// Packed dual-FMA (Blackwell f32x2 pipe — 2 fp32 FMAs per issue).
__device__ __forceinline__ void ffma2(ull& d, ull a, ull b) {
    asm("fma.rn.f32x2 %0, %1, %2, %0;" : "+l"(d) : "l"(a), "l"(b));
}

// exc[B][T] -> g_excT[T][B]
__global__ void transpose_exc(const float* __restrict__ exc) {
    __shared__ float tile[32][33];
    int t0 = blockIdx.x * 32, b0 = blockIdx.y * 32;
    int tx = threadIdx.x, ty = threadIdx.y;
#pragma unroll
    for (int i = 0; i < 32; i += 8)
        tile[ty + i][tx] = exc[(size_t)(b0 + ty + i) * TN + t0 + tx];
    __syncthreads();
#pragma unroll
    for (int i = 0; i < 32; i += 8)
        g_excT[(size_t)(t0 + ty + i) * BN + b0 + tx] = tile[tx][ty + i];
}

// Weight-stationary formulation, 8 muscles/CTA for 2x warp count.
// CTA = 64 threads (2 warps). Thread tid owns output neuron j = tid:
// W1 column (4 regs), b1, b2, and the whole W2 column as 32 packed f32x2
// registers. h is staged in smem, read with BROADCAST LDS.128.
// Lanes 0..3 of each warp own one muscle each (physics / layer-3 / RK4).
__global__ __launch_bounds__(64) void ode_kernel(
    const float* __restrict__ init, const float* __restrict__ tspan,
    const float* __restrict__ W1, const float* __restrict__ b1,
    const float* __restrict__ W2, const float* __restrict__ b2,
    const float* __restrict__ W3, const float* __restrict__ b3,
    float* __restrict__ out)
{
    __shared__ __align__(16) float h_s[MPC * 72];
    __shared__ __align__(16) float o_s[MPC * 72];
    __shared__ __align__(16) float x_s[MPC * 4];
    __shared__ __align__(16) float w3t[3][68];   // transposed W3, row-padded
    __shared__ __align__(16) float sb3[4];

    const int tid  = threadIdx.x;
    const int lane = tid & 31;
    const int warp = tid >> 5;
    const int jg   = tid;                 // output-neuron index 0..63

    // one-time weight staging
    for (int i = tid; i < 192; i += 64) w3t[i % 3][i / 3] = W3[i];
    if (tid < 3) sb3[tid] = b3[tid];
    if (tid == 3) sb3[3] = 0.0f;

    const float w10 = W1[jg], w11 = W1[64 + jg],
                w12 = W1[128 + jg], w13 = W1[192 + jg];
    const float b1j = b1[jg];
    const float b2j = b2[jg];
    ull w2p[32];
#pragma unroll
    for (int i = 0; i < 32; i++)
        w2p[i] = pack2(W2[(2 * i) * 64 + jg], W2[(2 * i + 1) * 64 + jg]);

    const bool owner = lane < 4;
    const int  mo = warp * 4 + lane;               // muscle owned (if owner)
    const int  bo = blockIdx.x * MPC + mo;

    float y0 = 0.f, y1 = 0.f, y2 = 0.f, ep = 0.f, tprev = 0.f;
    if (owner) {
        y0 = init[bo * 3 + 0];
        y1 = init[bo * 3 + 1];
        y2 = init[bo * 3 + 2];
        out[bo * 3 + 0] = y0; out[bo * 3 + 1] = y1; out[bo * 3 + 2] = y2;
        ep = g_excT[bo];                 // k1 at step 0 uses exc[:, 0]
        tprev = tspan[0];
        *(float4*)(x_s + mo * 4) = make_float4(y0, y1, y2, ep);
    }
    __syncthreads();

#pragma unroll 1
    for (int it = 0; it < TN - 1; it++) {
        float ec = 0.f, dt = 0.f, hd = 0.f;
        float a0 = y0, a1 = y1, a2 = y2;
        float s0 = 0.f, s1 = 0.f, s2 = 0.f;
        if (owner) {
            ec = g_excT[(size_t)it * BN + bo];     // exc[:, it] for k2/k3/k4
            float tnext = tspan[it + 1];
            dt = tnext - tprev;
            tprev = tnext;
            hd = 0.5f * dt;
        }

#pragma unroll 1
        for (int sg = 0; sg < 4; sg++) {
            // ---- slot 1: layer-1 (all threads) + physics (owner lanes) ----
#pragma unroll
            for (int m = 0; m < MPC; m++) {
                float4 x = *(const float4*)(x_s + m * 4);   // broadcast
                float t = fmaf(x.x, w10,
                          fmaf(x.y, w11,
                          fmaf(x.z, w12,
                          fmaf(x.w, w13, b1j))));
                h_s[m * 72 + jg] = tanha(t);
            }

            float k0 = 0.f, k1d = 0.f, k2d = 0.f, e = 0.f;
            if (owner) {
                e = (sg == 0) ? ep : ec;
                float lM   = fminf(fmaxf(a0, 0.0445f), 0.1424f);
                float act  = fminf(fmaxf(a1, 0.01f), 1.0f);
                float fat  = fminf(fmaxf(a2, 0.0f), 1.0f);
                float aeff = act * (1.0f - fat);
                // L0*sin(PENN0) = 0.089*sin(0.0873)
                float sinp = fminf(__fdividef(0.00775983457f, lM), 0.99f);
                float cosp = sqrtf(1.0f - sinp * sinp);
                // LMT_DEFAULT = 0.126 + 0.089*cos(0.0873)
                float lT   = 0.214661068f - lM * cosp;
                float epsT = (lT - 0.126f) * (1.0f / 0.126f);
                float fT   = (epsT > 0.0f) ? 0.2f * (__expf(35.0f * epsT) - 1.0f) : 0.0f;
                float lN   = lM * (1.0f / 0.089f);
                float ddv  = lN - 1.0f;
                float fL   = __expf(-ddv * ddv * (1.0f / 0.45f));
                float fPE  = (lN > 1.0f)
                           ? (__expf(ddv * (5.0f / 0.6f)) - 1.0f) * (1.0f / 147.4131591f)
                           : 0.0f;
                float fV   = __fdividef(__fdividef(fT, cosp) - fPE, aeff * fL + 0.001f);
                float vN   = fminf(fmaxf(__fdividef(fV - 1.0f, 1.0f + fabsf(fV) * 4.0f),
                                         -1.0f), 1.5f);
                k0   = 0.89f * vN;                        // VMAX*L0*vN
                float tau = (e > act) ? 0.01f * (0.5f + 1.5f * act)
                                      : __fdividef(0.04f, 0.5f + 1.5f * act);
                k1d  = __fdividef(e - act, tau);
                k2d  = 0.01f * aeff * (1.0f - fat) - 0.002f * (1.0f - aeff) * fat;
            }
            __syncthreads();

            // ---- slot 2: layer-2, weight-stationary, 2 muscles at a time ----
#pragma unroll 1
            for (int m = 0; m < MPC; m += 2) {
                const ulonglong2* hA = (const ulonglong2*)(h_s + m * 72);
                const ulonglong2* hB = (const ulonglong2*)(h_s + (m + 1) * 72);
                ull aA0 = 0, aA1 = 0, aB0 = 0, aB1 = 0;
#pragma unroll
                for (int q = 0; q < 16; q++) {
                    ulonglong2 hqA = hA[q];      // broadcast LDS.128
                    ulonglong2 hqB = hB[q];
                    ffma2(aA0, hqA.x, w2p[2 * q]);
                    ffma2(aA1, hqA.y, w2p[2 * q + 1]);
                    ffma2(aB0, hqB.x, w2p[2 * q]);
                    ffma2(aB1, hqB.y, w2p[2 * q + 1]);
                }
                float u0, u1, u2, u3;
                unpack2(aA0, u0, u1); unpack2(aA1, u2, u3);
                o_s[m * 72 + jg] = tanha(((u0 + u1) + (u2 + u3)) + b2j);
                unpack2(aB0, u0, u1); unpack2(aB1, u2, u3);
                o_s[(m + 1) * 72 + jg] = tanha(((u0 + u1) + (u2 + u3)) + b2j);
            }
            __syncthreads();

            // ---- slot 3: layer-3 + RK4 (owner lanes) ----
            if (owner) {
                const ulonglong2* orow = (const ulonglong2*)(o_s + mo * 72);
                const ulonglong2* w3r0 = (const ulonglong2*)(w3t[0]);
                const ulonglong2* w3r1 = (const ulonglong2*)(w3t[1]);
                const ulonglong2* w3r2 = (const ulonglong2*)(w3t[2]);
                ull P0 = 0, P1 = 0, P2 = 0;
#pragma unroll
                for (int q = 0; q < 16; q++) {
                    ulonglong2 oq = orow[q];
                    ulonglong2 wq0 = w3r0[q], wq1 = w3r1[q], wq2 = w3r2[q];
                    ffma2(P0, oq.x, wq0.x); ffma2(P0, oq.y, wq0.y);
                    ffma2(P1, oq.x, wq1.x); ffma2(P1, oq.y, wq1.y);
                    ffma2(P2, oq.x, wq2.x); ffma2(P2, oq.y, wq2.y);
                }
                float p0a, p0b, p1a, p1b, p2a, p2b;
                unpack2(P0, p0a, p0b);
                unpack2(P1, p1a, p1b);
                unpack2(P2, p2a, p2b);
                float p0 = p0a + p0b, p1 = p1a + p1b, p2 = p2a + p2b;

                k0  += 0.2f * (0.1f * tanha(p0 + sb3[0]));
                k1d += 0.2f * (0.1f * tanha(p1 + sb3[1]));
                k2d += 0.2f * (0.1f * tanha(p2 + sb3[2]));

                float wgt = (sg == 1 || sg == 2) ? 2.0f : 1.0f;
                s0 = fmaf(wgt, k0,  s0);
                s1 = fmaf(wgt, k1d, s1);
                s2 = fmaf(wgt, k2d, s2);

                if (sg < 3) {
                    float st = (sg < 2) ? hd : dt;
                    a0 = y0 + st * k0;
                    a1 = y1 + st * k1d;
                    a2 = y2 + st * k2d;
                    *(float4*)(x_s + mo * 4) = make_float4(a0, a1, a2, ec);
                } else {
                    float w6 = dt * (1.0f / 6.0f);
                    y0 += w6 * s0; y1 += w6 * s1; y2 += w6 * s2;
                    size_t o = (size_t)(it + 1) * (BN * 3) + (size_t)bo * 3;
                    out[o] = y0; out[o + 1] = y1; out[o + 2] = y2;
                    // next step's k1 excitation = this step's ec
                    *(float4*)(x_s + mo * 4) = make_float4(y0, y1, y2, ec);
                }
            }
            __syncthreads();
        }
        if (owner) ep = ec;
    }
}

extern "C" void kernel_launch(void* const* d_in, const int* in_sizes, int n_in,
                              void* d_out, int out_size) {
    const float* init = (const float*)d_in[0];
    const float* exc  = (const float*)d_in[1];
    const float* ts   = (const float*)d_in[2];
    const float* W1   = (const float*)d_in[3];
    const float* b1   = (const float*)d_in[4];
    const float* W2   = (const float*)d_in[5];
    const float* b2   = (const float*)d_in[6];
    const float* W3   = (const float*)d_in[7];
    const float* b3   = (const float*)d_in[8];
    float* out = (float*)d_out;

    dim3 tb(32, 8);
    dim3 tg(TN / 32, BN / 32);
    transpose_exc<<<tg, tb>>>(exc);
    ode_kernel<<<BN / MPC, 64>>>(init, ts, W1, b1, W2, b2, W3, b3, out);
}

// round 6
// speedup vs baseline: 2.5537x; 1.0033x over previous
#include <cuda_runtime.h>

typedef unsigned long long ull;

#define BN 8192
#define TN 2048
#define MPC 8    // muscles per CTA

// Transposed excitation scratch: [T][B] layout for coalesced per-step loads.
__device__ float g_excT[(size_t)TN * BN];

__device__ __forceinline__ float tanha(float x) {
    float y; asm("tanh.approx.f32 %0, %1;" : "=f"(y) : "f"(x)); return y;
}
__device__ __forceinline__ ull pack2(float lo, float hi) {
    ull r; asm("mov.b64 %0, {%1, %2};" : "=l"(r) : "f"(lo), "f"(hi)); return r;
}
__device__ __forceinline__ void unpack2(ull v, float& lo, float& hi) {
    asm("mov.b64 {%0, %1}, %2;" : "=f"(lo), "=f"(hi) : "l"(v));
}
// Packed dual-FMA (Blackwell f32x2 pipe — 2 fp32 FMAs per issue).
__device__ __forceinline__ void ffma2(ull& d, ull a, ull b) {
    asm("fma.rn.f32x2 %0, %1, %2, %0;" : "+l"(d) : "l"(a), "l"(b));
}

// exc[B][T] -> g_excT[T][B]
__global__ void transpose_exc(const float* __restrict__ exc) {
    __shared__ float tile[32][33];
    int t0 = blockIdx.x * 32, b0 = blockIdx.y * 32;
    int tx = threadIdx.x, ty = threadIdx.y;
#pragma unroll
    for (int i = 0; i < 32; i += 8)
        tile[ty + i][tx] = exc[(size_t)(b0 + ty + i) * TN + t0 + tx];
    __syncthreads();
#pragma unroll
    for (int i = 0; i < 32; i += 8)
        g_excT[(size_t)(t0 + ty + i) * BN + b0 + tx] = tile[tx][ty + i];
}

// Weight-stationary formulation, 8 muscles/CTA for 2x warp count.
// CTA = 64 threads (2 warps). Thread tid owns output neuron j = tid:
// W1 column (4 regs), b1, b2, and the whole W2 column as 32 packed f32x2
// registers. h is staged in smem, read with BROADCAST LDS.128.
// Lanes 0..3 of each warp own one muscle each (physics / layer-3 / RK4).
__global__ __launch_bounds__(64) void ode_kernel(
    const float* __restrict__ init, const float* __restrict__ tspan,
    const float* __restrict__ W1, const float* __restrict__ b1,
    const float* __restrict__ W2, const float* __restrict__ b2,
    const float* __restrict__ W3, const float* __restrict__ b3,
    float* __restrict__ out)
{
    __shared__ __align__(16) float h_s[MPC * 72];
    __shared__ __align__(16) float o_s[MPC * 72];
    __shared__ __align__(16) float x_s[MPC * 4];
    __shared__ __align__(16) float w3t[3][68];   // transposed W3, row-padded
    __shared__ __align__(16) float sb3[4];

    const int tid  = threadIdx.x;
    const int lane = tid & 31;
    const int warp = tid >> 5;
    const int jg   = tid;                 // output-neuron index 0..63

    // one-time weight staging
    for (int i = tid; i < 192; i += 64) w3t[i % 3][i / 3] = W3[i];
    if (tid < 3) sb3[tid] = b3[tid];
    if (tid == 3) sb3[3] = 0.0f;

    const float w10 = W1[jg], w11 = W1[64 + jg],
                w12 = W1[128 + jg], w13 = W1[192 + jg];
    const float b1j = b1[jg];
    const float b2j = b2[jg];
    ull w2p[32];
#pragma unroll
    for (int i = 0; i < 32; i++)
        w2p[i] = pack2(W2[(2 * i) * 64 + jg], W2[(2 * i + 1) * 64 + jg]);

    const bool owner = lane < 4;
    const int  mo = warp * 4 + lane;               // muscle owned (if owner)
    const int  bo = blockIdx.x * MPC + mo;

    float y0 = 0.f, y1 = 0.f, y2 = 0.f, ep = 0.f, tprev = 0.f;
    if (owner) {
        y0 = init[bo * 3 + 0];
        y1 = init[bo * 3 + 1];
        y2 = init[bo * 3 + 2];
        out[bo * 3 + 0] = y0; out[bo * 3 + 1] = y1; out[bo * 3 + 2] = y2;
        ep = g_excT[bo];                 // k1 at step 0 uses exc[:, 0]
        tprev = tspan[0];
        *(float4*)(x_s + mo * 4) = make_float4(y0, y1, y2, ep);
    }
    __syncthreads();

#pragma unroll 1
    for (int it = 0; it < TN - 1; it++) {
        float ec = 0.f, dt = 0.f, hd = 0.f;
        float a0 = y0, a1 = y1, a2 = y2;
        float s0 = 0.f, s1 = 0.f, s2 = 0.f;
        if (owner) {
            ec = g_excT[(size_t)it * BN + bo];     // exc[:, it] for k2/k3/k4
            float tnext = tspan[it + 1];
            dt = tnext - tprev;
            tprev = tnext;
            hd = 0.5f * dt;
        }

#pragma unroll 1
        for (int sg = 0; sg < 4; sg++) {
            // ---- slot 1: layer-1 (all threads) + physics (owner lanes) ----
#pragma unroll
            for (int m = 0; m < MPC; m++) {
                float4 x = *(const float4*)(x_s + m * 4);   // broadcast
                float t = fmaf(x.x, w10,
                          fmaf(x.y, w11,
                          fmaf(x.z, w12,
                          fmaf(x.w, w13, b1j))));
                h_s[m * 72 + jg] = tanha(t);
            }

            float k0 = 0.f, k1d = 0.f, k2d = 0.f, e = 0.f;
            if (owner) {
                e = (sg == 0) ? ep : ec;
                float lM   = fminf(fmaxf(a0, 0.0445f), 0.1424f);
                float act  = fminf(fmaxf(a1, 0.01f), 1.0f);
                float fat  = fminf(fmaxf(a2, 0.0f), 1.0f);
                float aeff = act * (1.0f - fat);
                // L0*sin(PENN0) = 0.089*sin(0.0873)
                float sinp = fminf(__fdividef(0.00775983457f, lM), 0.99f);
                float cosp = sqrtf(1.0f - sinp * sinp);
                // LMT_DEFAULT = 0.126 + 0.089*cos(0.0873)
                float lT   = 0.214661068f - lM * cosp;
                float epsT = (lT - 0.126f) * (1.0f / 0.126f);
                float fT   = (epsT > 0.0f) ? 0.2f * (__expf(35.0f * epsT) - 1.0f) : 0.0f;
                float lN   = lM * (1.0f / 0.089f);
                float ddv  = lN - 1.0f;
                float fL   = __expf(-ddv * ddv * (1.0f / 0.45f));
                float fPE  = (lN > 1.0f)
                           ? (__expf(ddv * (5.0f / 0.6f)) - 1.0f) * (1.0f / 147.4131591f)
                           : 0.0f;
                float fV   = __fdividef(__fdividef(fT, cosp) - fPE, aeff * fL + 0.001f);
                float vN   = fminf(fmaxf(__fdividef(fV - 1.0f, 1.0f + fabsf(fV) * 4.0f),
                                         -1.0f), 1.5f);
                k0   = 0.89f * vN;                        // VMAX*L0*vN
                float tau = (e > act) ? 0.01f * (0.5f + 1.5f * act)
                                      : __fdividef(0.04f, 0.5f + 1.5f * act);
                k1d  = __fdividef(e - act, tau);
                k2d  = 0.01f * aeff * (1.0f - fat) - 0.002f * (1.0f - aeff) * fat;
            }
            __syncthreads();

            // ---- slot 2: layer-2, weight-stationary, 2 muscles at a time ----
#pragma unroll 1
            for (int m = 0; m < MPC; m += 2) {
                const ulonglong2* hA = (const ulonglong2*)(h_s + m * 72);
                const ulonglong2* hB = (const ulonglong2*)(h_s + (m + 1) * 72);
                ull aA0 = 0, aA1 = 0, aB0 = 0, aB1 = 0;
#pragma unroll
                for (int q = 0; q < 16; q++) {
                    ulonglong2 hqA = hA[q];      // broadcast LDS.128
                    ulonglong2 hqB = hB[q];
                    ffma2(aA0, hqA.x, w2p[2 * q]);
                    ffma2(aA1, hqA.y, w2p[2 * q + 1]);
                    ffma2(aB0, hqB.x, w2p[2 * q]);
                    ffma2(aB1, hqB.y, w2p[2 * q + 1]);
                }
                float u0, u1, u2, u3;
                unpack2(aA0, u0, u1); unpack2(aA1, u2, u3);
                o_s[m * 72 + jg] = tanha(((u0 + u1) + (u2 + u3)) + b2j);
                unpack2(aB0, u0, u1); unpack2(aB1, u2, u3);
                o_s[(m + 1) * 72 + jg] = tanha(((u0 + u1) + (u2 + u3)) + b2j);
            }
            __syncthreads();

            // ---- slot 3: layer-3 + RK4 (owner lanes) ----
            if (owner) {
                const ulonglong2* orow = (const ulonglong2*)(o_s + mo * 72);
                const ulonglong2* w3r0 = (const ulonglong2*)(w3t[0]);
                const ulonglong2* w3r1 = (const ulonglong2*)(w3t[1]);
                const ulonglong2* w3r2 = (const ulonglong2*)(w3t[2]);
                ull P0 = 0, P1 = 0, P2 = 0;
#pragma unroll
                for (int q = 0; q < 16; q++) {
                    ulonglong2 oq = orow[q];
                    ulonglong2 wq0 = w3r0[q], wq1 = w3r1[q], wq2 = w3r2[q];
                    ffma2(P0, oq.x, wq0.x); ffma2(P0, oq.y, wq0.y);
                    ffma2(P1, oq.x, wq1.x); ffma2(P1, oq.y, wq1.y);
                    ffma2(P2, oq.x, wq2.x); ffma2(P2, oq.y, wq2.y);
                }
                float p0a, p0b, p1a, p1b, p2a, p2b;
                unpack2(P0, p0a, p0b);
                unpack2(P1, p1a, p1b);
                unpack2(P2, p2a, p2b);
                float p0 = p0a + p0b, p1 = p1a + p1b, p2 = p2a + p2b;

                k0  += 0.2f * (0.1f * tanha(p0 + sb3[0]));
                k1d += 0.2f * (0.1f * tanha(p1 + sb3[1]));
                k2d += 0.2f * (0.1f * tanha(p2 + sb3[2]));

                float wgt = (sg == 1 || sg == 2) ? 2.0f : 1.0f;
                s0 = fmaf(wgt, k0,  s0);
                s1 = fmaf(wgt, k1d, s1);
                s2 = fmaf(wgt, k2d, s2);

                if (sg < 3) {
                    float st = (sg < 2) ? hd : dt;
                    a0 = y0 + st * k0;
                    a1 = y1 + st * k1d;
                    a2 = y2 + st * k2d;
                    *(float4*)(x_s + mo * 4) = make_float4(a0, a1, a2, ec);
                } else {
                    float w6 = dt * (1.0f / 6.0f);
                    y0 += w6 * s0; y1 += w6 * s1; y2 += w6 * s2;
                    size_t o = (size_t)(it + 1) * (BN * 3) + (size_t)bo * 3;
                    out[o] = y0; out[o + 1] = y1; out[o + 2] = y2;
                    // next step's k1 excitation = this step's ec
                    *(float4*)(x_s + mo * 4) = make_float4(y0, y1, y2, ec);
                }
            }
            __syncthreads();
        }
        if (owner) ep = ec;
    }
}

extern "C" void kernel_launch(void* const* d_in, const int* in_sizes, int n_in,
                              void* d_out, int out_size) {
    const float* init = (const float*)d_in[0];
    const float* exc  = (const float*)d_in[1];
    const float* ts   = (const float*)d_in[2];
    const float* W1   = (const float*)d_in[3];
    const float* b1   = (const float*)d_in[4];
    const float* W2   = (const float*)d_in[5];
    const float* b2   = (const float*)d_in[6];
    const float* W3   = (const float*)d_in[7];
    const float* b3   = (const float*)d_in[8];
    float* out = (float*)d_out;

    dim3 tb(32, 8);
    dim3 tg(TN / 32, BN / 32);
    transpose_exc<<<tg, tb>>>(exc);
    ode_kernel<<<BN / MPC, 64>>>(init, ts, W1, b1, W2, b2, W3, b3, out);
}